// round 9
// baseline (speedup 1.0000x reference)
#include <cuda_runtime.h>
#include <cuda_fp16.h>
#include <cstdint>

// Problem constants
#define B_ 4
#define T_ 2048
#define C_ 1024
#define H_ 16
#define D_ 64
#define BT_ (B_ * T_)            // 8192
#define KDIM 1024

#define QSCALE 0.18033688011112042f   // 0.125 * log2(e)

// ---------------------------------------------------------------------------
// Scratch (device globals — no allocation allowed). All splits fp16 hi/lo.
// ---------------------------------------------------------------------------
__device__ __half g_xh[(size_t)BT_ * KDIM];    // x hi/lo
__device__ __half g_xl[(size_t)BT_ * KDIM];
__device__ __half g_wh[(size_t)3 * C_ * KDIM]; // W_attn^T hi [3072][1024]
__device__ __half g_ph[(size_t)C_ * KDIM];     // W_proj^T hi [1024][1024]
__device__ __half g_ah[(size_t)BT_ * KDIM];    // attn-out hi/lo [B,T,C]
__device__ __half g_al[(size_t)BT_ * KDIM];
// Q hi/lo, K hi, V hi in [B,H,T,D]; q pre-scaled by QSCALE
__device__ __half g_qh[(size_t)BT_ * C_];
__device__ __half g_ql[(size_t)BT_ * C_];
__device__ __half g_kh[(size_t)BT_ * C_];
__device__ __half g_vh[(size_t)BT_ * C_];

// ---------------------------------------------------------------------------
// helpers (sm_80-era PTX — legal at compute_103 base)
// ---------------------------------------------------------------------------
__device__ __forceinline__ uint32_t s2u(const void* p) {
    uint32_t a;
    asm("{ .reg .u64 t; cvta.to.shared.u64 t, %1; cvt.u32.u64 %0, t; }" : "=r"(a) : "l"(p));
    return a;
}
__device__ __forceinline__ uint32_t swz(uint32_t off) {    // SW128 (128B rows)
    return off ^ ((off >> 3) & 0x70);
}
__device__ __forceinline__ uint32_t swz64(uint32_t off) {  // SW64 (64B rows)
    return off ^ ((off >> 3) & 0x30);
}
__device__ __forceinline__ void cp_async16(uint32_t dst, const void* src) {
    asm volatile("cp.async.cg.shared.global [%0], [%1], 16;" :: "r"(dst), "l"(src) : "memory");
}
__device__ __forceinline__ void ldsm4(uint32_t* r, uint32_t addr) {
    asm volatile("ldmatrix.sync.aligned.m8n8.x4.shared.b16 {%0,%1,%2,%3}, [%4];"
                 : "=r"(r[0]), "=r"(r[1]), "=r"(r[2]), "=r"(r[3]) : "r"(addr));
}
__device__ __forceinline__ void ldsm4t(uint32_t* r, uint32_t addr) {
    asm volatile("ldmatrix.sync.aligned.m8n8.x4.trans.shared.b16 {%0,%1,%2,%3}, [%4];"
                 : "=r"(r[0]), "=r"(r[1]), "=r"(r[2]), "=r"(r[3]) : "r"(addr));
}
__device__ __forceinline__ void mma2(float* c, const uint32_t* a, uint32_t b0, uint32_t b1) {
    asm volatile(
        "mma.sync.aligned.m16n8k16.row.col.f32.f16.f16.f32 "
        "{%0,%1,%2,%3}, {%4,%5,%6,%7}, {%8,%9}, {%0,%1,%2,%3};"
        : "+f"(c[0]), "+f"(c[1]), "+f"(c[2]), "+f"(c[3])
        : "r"(a[0]), "r"(a[1]), "r"(a[2]), "r"(a[3]), "r"(b0), "r"(b1));
}
__device__ __forceinline__ uint32_t packh2(float x, float y) {
    __half2 t; t.x = __float2half(x); t.y = __float2half(y);
    return *(uint32_t*)&t;
}
__device__ __forceinline__ void packsplit(float x, float y, uint32_t& hi, uint32_t& lo) {
    __half2 h, l;
    h.x = __float2half(x); h.y = __float2half(y);
    l.x = __float2half(x - __half2float(h.x));
    l.y = __float2half(y - __half2float(h.y));
    hi = *(uint32_t*)&h; lo = *(uint32_t*)&l;
}
__device__ __forceinline__ float qred_max(float v) {
    v = fmaxf(v, __shfl_xor_sync(~0u, v, 1));
    return fmaxf(v, __shfl_xor_sync(~0u, v, 2));
}
__device__ __forceinline__ float qred_sum(float v) {
    v += __shfl_xor_sync(~0u, v, 1);
    return v + __shfl_xor_sync(~0u, v, 2);
}

// ---------------------------------------------------------------------------
// Fused conversion kernel (one launch):
//  blocks [0,1024):    x fp32 -> g_xh/g_xl
//  blocks [1024,4096): W_attn [1024,3072] -> g_wh [3072][1024] (fp16 hi)
//  blocks [4096,5120): W_proj [1024,1024] -> g_ph [1024][1024]
// ---------------------------------------------------------------------------
__global__ __launch_bounds__(256)
void convert_all(const float* __restrict__ x,
                 const float* __restrict__ Wattn,
                 const float* __restrict__ Wproj)
{
    const int blk = blockIdx.x;
    if (blk < 1024) {
        const size_t n4 = (size_t)BT_ * KDIM / 4;
        for (size_t i = (size_t)blk * 256 + threadIdx.x; i < n4; i += (size_t)1024 * 256) {
            float4 v = ((const float4*)x)[i];
            uint32_t h0, l0, h1, l1;
            packsplit(v.x, v.y, h0, l0);
            packsplit(v.z, v.w, h1, l1);
            ((uint32_t*)g_xh)[2 * i] = h0; ((uint32_t*)g_xh)[2 * i + 1] = h1;
            ((uint32_t*)g_xl)[2 * i] = l0; ((uint32_t*)g_xl)[2 * i + 1] = l1;
        }
    } else {
        const int W = (blk < 4096) ? 0 : 1;
        const int bidx = W ? (blk - 4096) : (blk - 1024);
        const int NBX = W ? 32 : 96;
        const int NC = W ? C_ : 3 * C_;
        const float* src = W ? Wproj : Wattn;
        __half* dh = W ? g_ph : g_wh;
        const int bx = bidx % NBX;
        const int by = bidx / NBX;
        const int tx = threadIdx.x & 31;
        const int ty = threadIdx.x >> 5;
        __shared__ float tile[32][33];
        const int xcol = bx * 32 + tx;
        const int y0 = by * 32;
#pragma unroll
        for (int j = 0; j < 32; j += 8)
            tile[ty + j][tx] = src[(size_t)(y0 + ty + j) * NC + xcol];
        __syncthreads();
        const int ox = y0 + tx;
        const int oyb = bx * 32;
#pragma unroll
        for (int j = 0; j < 32; j += 8)
            dh[(size_t)(oyb + ty + j) * KDIM + ox] = __float2half(tile[tx][ty + j]);
    }
}

// ---------------------------------------------------------------------------
// fp16x2 GEMM via mma.sync: D = A x B^T, A split hi/lo, B hi only.
// CTA tile 128x128, warp tile 32x64 (4M x 2N), K_chunk=32 elements,
// 4-stage ring, ONE syncthreads per chunk, 2 CTAs/SM.
// Stage (24KB): [Ah 8K][Al 8K][Bh 8K], 64B rows, SW64 swizzle.
// ---------------------------------------------------------------------------
#define SM_STAGE 24576
#define SMEM_GEMM_BYTES 98304    // 4 stages
#define NCH 32                   // 1024 / 32

template <int MODE>
__global__ __launch_bounds__(256, 2)
void mma_gemm(const float* __restrict__ bias,
              float* __restrict__ o0, float* __restrict__ o1, float* __restrict__ o2)
{
    extern __shared__ __align__(1024) char smem[];
    const uint32_t sm = s2u(smem);
    const int tid = threadIdx.x;
    const int wid = tid >> 5;
    const int lid = tid & 31;
    const int n0 = blockIdx.x * 128;
    const int m0 = blockIdx.y * 128;

    const __half* Ahp = (MODE == 0) ? g_xh : g_ah;
    const __half* Alp = (MODE == 0) ? g_xl : g_al;
    const __half* Bhp = (MODE == 0) ? g_wh : g_ph;

    // copy plan: 1536 x 16B per stage, 6 per thread
    auto issue_loads = [&](int c, int s) {
        const uint32_t sb = sm + (uint32_t)s * SM_STAGE;
#pragma unroll
        for (int r = 0; r < 6; r++) {
            const int id = tid + r * 256;
            const int bsel = id >> 9;            // 0:Ah 1:Al 2:Bh
            const int row = (id >> 2) & 127;
            const int c16 = id & 3;
            const uint32_t off = swz64((uint32_t)(row * 64 + c16 * 16));
            const __half* base;
            if (bsel == 0)      base = Ahp + (size_t)(m0 + row) * KDIM;
            else if (bsel == 1) base = Alp + (size_t)(m0 + row) * KDIM;
            else                base = Bhp + (size_t)(n0 + row) * KDIM;
            cp_async16(sb + bsel * 8192 + off, base + c * 32 + c16 * 8);
        }
        asm volatile("cp.async.commit_group;" ::: "memory");
    };

    const int wm = (wid & 3) * 32;       // warp M origin (4 rows of warps)
    const int wn = (wid >> 2) * 64;      // warp N origin (2 cols of warps)
    const int g = lid >> 2;
    const int tig = lid & 3;
    const int aRow = lid & 15;
    const int aKb = (lid >> 4) * 16;
    const int bRow = ((lid >> 4) & 1) * 8 + (lid & 7);
    const int bKb = ((lid >> 3) & 1) * 16;

    float Cr[2][8][4];                   // [mi][n8 slice][quad]
#pragma unroll
    for (int mi = 0; mi < 2; mi++)
#pragma unroll
        for (int j = 0; j < 8; j++)
#pragma unroll
            for (int qi = 0; qi < 4; qi++) Cr[mi][j][qi] = 0.f;

    issue_loads(0, 0);
    issue_loads(1, 1);
    issue_loads(2, 2);

    for (int c = 0; c < NCH; c++) {
        const int s = c & 3;
        if (c <= NCH - 3)      asm volatile("cp.async.wait_group 2;" ::: "memory");
        else if (c == NCH - 2) asm volatile("cp.async.wait_group 1;" ::: "memory");
        else                   asm volatile("cp.async.wait_group 0;" ::: "memory");
        __syncthreads();
        // stage (c+3)&3 == (c-1)&3: fully consumed before this sync
        if (c + 3 < NCH) issue_loads(c + 3, (c + 3) & 3);

        const uint32_t sb = sm + (uint32_t)s * SM_STAGE;
        const uint32_t tAh = sb, tAl = sb + 8192, tBh = sb + 16384;

#pragma unroll
        for (int ks = 0; ks < 2; ks++) {
            const int kb = ks * 32;
            uint32_t ah[2][4], al[2][4], bh[4][4];
#pragma unroll
            for (int mi = 0; mi < 2; mi++) {
                const uint32_t off = swz64((uint32_t)((wm + mi * 16 + aRow) * 64 + kb + aKb));
                ldsm4(ah[mi], tAh + off);
                ldsm4(al[mi], tAl + off);
            }
#pragma unroll
            for (int jp = 0; jp < 4; jp++) {
                const uint32_t off = swz64((uint32_t)((wn + jp * 16 + bRow) * 64 + kb + bKb));
                ldsm4(bh[jp], tBh + off);
            }
#pragma unroll
            for (int mi = 0; mi < 2; mi++)
#pragma unroll
                for (int j = 0; j < 8; j++) {
                    const int jp = j >> 1, o = (j & 1) * 2;
                    mma2(Cr[mi][j], ah[mi], bh[jp][o], bh[jp][o + 1]);
                    mma2(Cr[mi][j], al[mi], bh[jp][o], bh[jp][o + 1]);
                }
        }
    }

    // ---- epilogue ----
#pragma unroll
    for (int mi = 0; mi < 2; mi++)
#pragma unroll
        for (int j = 0; j < 8; j++) {
            const int col = n0 + wn + (j >> 1) * 16 + (j & 1) * 8 + tig * 2;
            const float2 bb = *(const float2*)(bias + col);
#pragma unroll
            for (int half = 0; half < 2; half++) {
                const int row = m0 + wm + mi * 16 + g + half * 8;
                float2 v;
                v.x = Cr[mi][j][half * 2 + 0] + bb.x;
                v.y = Cr[mi][j][half * 2 + 1] + bb.y;
                if (MODE == 0) {
                    const int seg = col >> 10;
                    const int c0 = col & 1023;
                    const int h = c0 >> 6;
                    const int dd = c0 & 63;
                    const int b = row >> 11;
                    const int t = row & (T_ - 1);
                    const size_t idx = ((size_t)(b * H_ + h) * T_ + t) * D_ + dd;
                    if (seg == 0) {
                        uint32_t hi, lo;
                        packsplit(v.x * QSCALE, v.y * QSCALE, hi, lo);
                        *(uint32_t*)&g_qh[idx] = hi;
                        *(uint32_t*)&g_ql[idx] = lo;
                    } else if (seg == 1) {
                        *(float2*)&o1[idx] = v;
                        *(uint32_t*)&g_kh[idx] = packh2(v.x, v.y);
                    } else {
                        *(float2*)&o2[idx] = v;
                        *(uint32_t*)&g_vh[idx] = packh2(v.x, v.y);
                    }
                } else {
                    *(float2*)&o0[(size_t)row * C_ + col] = v;
                }
            }
        }
}

// ---------------------------------------------------------------------------
// Flash attention via mma.sync fp16x2; 3-stage KV (single sync per tile),
// 2 CTAs/SM, pipelined K/V fragment loads. (unchanged from R8)
// ---------------------------------------------------------------------------
#define AT_SMEM 81920            // Q 32K + 3 stages x 16K

__global__ __launch_bounds__(256, 2)
void attn_mma()
{
    extern __shared__ __align__(1024) char smem[];
    const uint32_t sm = s2u(smem);
    const int tid = threadIdx.x;
    const int wid = tid >> 5;
    const int lid = tid & 31;
    const int qb = 15 - blockIdx.x;          // heavy CTAs first
    const int bh = blockIdx.y;
    const size_t base_qkv = (size_t)bh * T_ * D_;
    const int nt = 2 * qb + 2;

#pragma unroll
    for (int r = 0; r < 8; r++) {
        const int id = tid + r * 256;
        const int bsel = id >> 10;
        const int row = (id >> 3) & 127;
        const int c16 = id & 7;
        const uint32_t dst = sm + bsel * 16384 + swz((uint32_t)(row * 128 + c16 * 16));
        const __half* src = (bsel ? g_ql : g_qh) + base_qkv
                            + (size_t)(qb * 128 + row) * D_ + c16 * 8;
        cp_async16(dst, src);
    }
    auto issue_kv = [&](int kt, int s) {
        const uint32_t sb = sm + 32768 + (uint32_t)s * 16384;
#pragma unroll
        for (int r = 0; r < 4; r++) {
            const int id = tid + r * 256;
            const int bsel = id >> 9;        // 0 Kh 1 Vh
            const int row = (id >> 3) & 63;
            const int c16 = id & 7;
            const uint32_t dst = sb + bsel * 8192 + swz((uint32_t)(row * 128 + c16 * 16));
            const __half* src = (bsel ? g_vh : g_kh) + base_qkv
                                + (size_t)(kt * 64 + row) * D_ + c16 * 8;
            cp_async16(dst, src);
        }
        asm volatile("cp.async.commit_group;" ::: "memory");
    };
    issue_kv(0, 0);
    issue_kv(1, 1);

    const int g = lid >> 2;
    const int t2 = (lid & 3) * 2;
    const int lrow16 = lid & 15;
    const int lhi = (lid >> 4) * 16;

    uint32_t qh[4][4], ql[4][4];
    float cfr[8][4], ofr[8][4];
    float mrow0 = -1e30f, mrow1 = -1e30f, lrow0 = 0.f, lrow1 = 0.f;
#pragma unroll
    for (int j = 0; j < 8; j++)
#pragma unroll
        for (int qi = 0; qi < 4; qi++) ofr[j][qi] = 0.f;

    for (int kb = 0; kb < nt; kb++) {
        const int s = kb % 3;
        if (kb + 1 < nt) asm volatile("cp.async.wait_group 1;" ::: "memory");
        else             asm volatile("cp.async.wait_group 0;" ::: "memory");
        __syncthreads();
        if (kb + 2 < nt) issue_kv(kb + 2, (kb + 2) % 3);
        if (kb == 0) {
#pragma unroll
            for (int kc = 0; kc < 4; kc++) {
                const uint32_t off = swz((uint32_t)((wid * 16 + lrow16) * 128 + kc * 32 + lhi));
                ldsm4(qh[kc], sm + off);
                ldsm4(ql[kc], sm + 16384 + off);
            }
        }
        const uint32_t kvb = sm + 32768 + (uint32_t)s * 16384;

        // ---- S = Q K^T (pipelined K frags, 2 buffers) ----
#pragma unroll
        for (int j = 0; j < 8; j++)
#pragma unroll
            for (int qi = 0; qi < 4; qi++) cfr[j][qi] = 0.f;
#pragma unroll
        for (int kc = 0; kc < 4; kc++) {
            uint32_t khb[2][4];
            auto LK = [&](int jp, int bp) {
                const uint32_t off = swz((uint32_t)((jp * 16 + lrow16) * 128 + kc * 32 + lhi));
                ldsm4(khb[bp], kvb + off);
            };
            auto MS = [&](int jp, int bp) {
                mma2(cfr[2 * jp],     qh[kc], khb[bp][0], khb[bp][2]);
                mma2(cfr[2 * jp],     ql[kc], khb[bp][0], khb[bp][2]);
                mma2(cfr[2 * jp + 1], qh[kc], khb[bp][1], khb[bp][3]);
                mma2(cfr[2 * jp + 1], ql[kc], khb[bp][1], khb[bp][3]);
            };
            LK(0, 0); LK(1, 1);
            MS(0, 0); LK(2, 0);
            MS(1, 1); LK(3, 1);
            MS(2, 0);
            MS(3, 1);
        }

        // ---- causal mask (diagonal tiles only) ----
        if (kb >= 2 * qb) {
            const int qr = qb * 128 + wid * 16 + g;
            const int kv0 = kb * 64;
#pragma unroll
            for (int j = 0; j < 8; j++) {
                const int col = kv0 + j * 8 + t2;
#pragma unroll
                for (int qi = 0; qi < 4; qi++) {
                    const int row = qr + ((qi >> 1) << 3);
                    if (col + (qi & 1) > row) cfr[j][qi] = -1e30f;
                }
            }
        }

        // ---- online softmax (log2 domain) ----
        float mx0 = -1e30f, mx1 = -1e30f;
#pragma unroll
        for (int j = 0; j < 8; j++) {
            mx0 = fmaxf(mx0, fmaxf(cfr[j][0], cfr[j][1]));
            mx1 = fmaxf(mx1, fmaxf(cfr[j][2], cfr[j][3]));
        }
        mx0 = qred_max(mx0);
        mx1 = qred_max(mx1);
        const float mn0 = fmaxf(mrow0, mx0), mn1 = fmaxf(mrow1, mx1);
        const float al0 = exp2f(mrow0 - mn0), al1 = exp2f(mrow1 - mn1);
        mrow0 = mn0; mrow1 = mn1;
        float s0 = 0.f, s1 = 0.f;
#pragma unroll
        for (int j = 0; j < 8; j++) {
            cfr[j][0] = exp2f(cfr[j][0] - mn0);
            cfr[j][1] = exp2f(cfr[j][1] - mn0);
            cfr[j][2] = exp2f(cfr[j][2] - mn1);
            cfr[j][3] = exp2f(cfr[j][3] - mn1);
            s0 += cfr[j][0] + cfr[j][1];
            s1 += cfr[j][2] + cfr[j][3];
        }
        s0 = qred_sum(s0);
        s1 = qred_sum(s1);
        lrow0 = lrow0 * al0 + s0;
        lrow1 = lrow1 * al1 + s1;
#pragma unroll
        for (int j = 0; j < 8; j++) {
            ofr[j][0] *= al0; ofr[j][1] *= al0;
            ofr[j][2] *= al1; ofr[j][3] *= al1;
        }

        // ---- O += P V (pipelined V frags, 2 buffers) ----
#pragma unroll
        for (int kc = 0; kc < 4; kc++) {
            uint32_t ph[4], pl[4];
            packsplit(cfr[2 * kc][0],     cfr[2 * kc][1],     ph[0], pl[0]);
            packsplit(cfr[2 * kc][2],     cfr[2 * kc][3],     ph[1], pl[1]);
            packsplit(cfr[2 * kc + 1][0], cfr[2 * kc + 1][1], ph[2], pl[2]);
            packsplit(cfr[2 * kc + 1][2], cfr[2 * kc + 1][3], ph[3], pl[3]);
            uint32_t vb[2][4];
            auto LV = [&](int nc, int bp) {
                const uint32_t off = swz((uint32_t)((kc * 16 + lrow16) * 128 + nc * 32 + lhi));
                ldsm4t(vb[bp], kvb + 8192 + off);
            };
            auto MV = [&](int nc, int bp) {
                mma2(ofr[2 * nc],     ph, vb[bp][0], vb[bp][1]);
                mma2(ofr[2 * nc],     pl, vb[bp][0], vb[bp][1]);
                mma2(ofr[2 * nc + 1], ph, vb[bp][2], vb[bp][3]);
                mma2(ofr[2 * nc + 1], pl, vb[bp][2], vb[bp][3]);
            };
            LV(0, 0); LV(1, 1);
            MV(0, 0); LV(2, 0);
            MV(1, 1); LV(3, 1);
            MV(2, 0);
            MV(3, 1);
        }
    }

    // ---- epilogue: write hi/lo fp16 into [B,T,C] for proj GEMM ----
    const float inv0 = 1.f / lrow0, inv1 = 1.f / lrow1;
    const int b = bh >> 4, h = bh & 15;
    const int t0 = qb * 128 + wid * 16 + g;
#pragma unroll
    for (int j = 0; j < 8; j++) {
        const int d = j * 8 + t2;
        const size_t i0 = ((size_t)(b * T_ + t0)) * C_ + h * 64 + d;
        const size_t i1 = i0 + (size_t)8 * C_;
        uint32_t hi, lo;
        packsplit(ofr[j][0] * inv0, ofr[j][1] * inv0, hi, lo);
        *(uint32_t*)&g_ah[i0] = hi;
        *(uint32_t*)&g_al[i0] = lo;
        packsplit(ofr[j][2] * inv1, ofr[j][3] * inv1, hi, lo);
        *(uint32_t*)&g_ah[i1] = hi;
        *(uint32_t*)&g_al[i1] = lo;
    }
}

// ---------------------------------------------------------------------------
// Launch. Inputs: x, mask, W_attn, b_attn, W_proj, b_proj.
// Output: [out (B,T,C) | k (B,H,T,D) | v (B,H,T,D)] fp32.
// ---------------------------------------------------------------------------
extern "C" void kernel_launch(void* const* d_in, const int* in_sizes, int n_in,
                              void* d_out, int out_size)
{
    (void)in_sizes; (void)n_in; (void)out_size;
    const float* x      = (const float*)d_in[0];
    const float* W_attn = (const float*)d_in[2];
    const float* b_attn = (const float*)d_in[3];
    const float* W_proj = (const float*)d_in[4];
    const float* b_proj = (const float*)d_in[5];

    float* out  = (float*)d_out;
    float* kout = out + (size_t)B_ * H_ * T_ * D_;
    float* vout = kout + (size_t)B_ * H_ * T_ * D_;

    cudaFuncSetAttribute(mma_gemm<0>, cudaFuncAttributeMaxDynamicSharedMemorySize,
                         SMEM_GEMM_BYTES);
    cudaFuncSetAttribute(mma_gemm<1>, cudaFuncAttributeMaxDynamicSharedMemorySize,
                         SMEM_GEMM_BYTES);
    cudaFuncSetAttribute(attn_mma, cudaFuncAttributeMaxDynamicSharedMemorySize,
                         AT_SMEM);

    // 1) fused conversions (x split + both weight transposes)
    convert_all<<<5120, 256>>>(x, W_attn, W_proj);

    // 2) QKV GEMM + bias + scatter (tile 128x128 -> grid 24x64)
    mma_gemm<0><<<dim3(24, 64), 256, SMEM_GEMM_BYTES>>>(b_attn, nullptr, kout, vout);

    // 3) causal flash attention (tensor cores) -> g_ah/g_al
    attn_mma<<<dim3(16, 64), 256, AT_SMEM>>>();

    // 4) proj GEMM (grid 8x64)
    mma_gemm<1><<<dim3(8, 64), 256, SMEM_GEMM_BYTES>>>(b_proj, out, nullptr, nullptr);
}

// round 10
// speedup vs baseline: 1.1237x; 1.1237x over previous
#include <cuda_runtime.h>
#include <cuda_fp16.h>
#include <cstdint>

// Problem constants
#define B_ 4
#define T_ 2048
#define C_ 1024
#define H_ 16
#define D_ 64
#define BT_ (B_ * T_)            // 8192
#define KDIM 1024

#define QSCALE 0.18033688011112042f   // 0.125 * log2(e)

// ---------------------------------------------------------------------------
// Scratch (device globals — no allocation allowed). All splits fp16.
// ---------------------------------------------------------------------------
__device__ __half g_xh[(size_t)BT_ * KDIM];    // x hi/lo
__device__ __half g_xl[(size_t)BT_ * KDIM];
__device__ __half g_wh[(size_t)3 * C_ * KDIM]; // W_attn^T hi [3072][1024]
__device__ __half g_ph[(size_t)C_ * KDIM];     // W_proj^T hi [1024][1024]
__device__ __half g_ah[(size_t)BT_ * KDIM];    // attn-out hi/lo [B,T,C]
__device__ __half g_al[(size_t)BT_ * KDIM];
// Q (fp16, pre-scaled by QSCALE), K hi, V hi in [B,H,T,D]
__device__ __half g_qh[(size_t)BT_ * C_];
__device__ __half g_kh[(size_t)BT_ * C_];
__device__ __half g_vh[(size_t)BT_ * C_];

// ---------------------------------------------------------------------------
// helpers (sm_80-era PTX — legal at compute_103 base)
// ---------------------------------------------------------------------------
__device__ __forceinline__ uint32_t s2u(const void* p) {
    uint32_t a;
    asm("{ .reg .u64 t; cvta.to.shared.u64 t, %1; cvt.u32.u64 %0, t; }" : "=r"(a) : "l"(p));
    return a;
}
__device__ __forceinline__ uint32_t swz(uint32_t off) {   // SW128
    return off ^ ((off >> 3) & 0x70);
}
__device__ __forceinline__ void cp_async16(uint32_t dst, const void* src) {
    asm volatile("cp.async.cg.shared.global [%0], [%1], 16;" :: "r"(dst), "l"(src) : "memory");
}
__device__ __forceinline__ void ldsm4(uint32_t* r, uint32_t addr) {
    asm volatile("ldmatrix.sync.aligned.m8n8.x4.shared.b16 {%0,%1,%2,%3}, [%4];"
                 : "=r"(r[0]), "=r"(r[1]), "=r"(r[2]), "=r"(r[3]) : "r"(addr));
}
__device__ __forceinline__ void ldsm4t(uint32_t* r, uint32_t addr) {
    asm volatile("ldmatrix.sync.aligned.m8n8.x4.trans.shared.b16 {%0,%1,%2,%3}, [%4];"
                 : "=r"(r[0]), "=r"(r[1]), "=r"(r[2]), "=r"(r[3]) : "r"(addr));
}
__device__ __forceinline__ void mma2(float* c, const uint32_t* a, uint32_t b0, uint32_t b1) {
    asm volatile(
        "mma.sync.aligned.m16n8k16.row.col.f32.f16.f16.f32 "
        "{%0,%1,%2,%3}, {%4,%5,%6,%7}, {%8,%9}, {%0,%1,%2,%3};"
        : "+f"(c[0]), "+f"(c[1]), "+f"(c[2]), "+f"(c[3])
        : "r"(a[0]), "r"(a[1]), "r"(a[2]), "r"(a[3]), "r"(b0), "r"(b1));
}
__device__ __forceinline__ uint32_t packh2(float x, float y) {
    __half2 t; t.x = __float2half(x); t.y = __float2half(y);
    return *(uint32_t*)&t;
}
__device__ __forceinline__ void packsplit(float x, float y, uint32_t& hi, uint32_t& lo) {
    __half2 h, l;
    h.x = __float2half(x); h.y = __float2half(y);
    l.x = __float2half(x - __half2float(h.x));
    l.y = __float2half(y - __half2float(h.y));
    hi = *(uint32_t*)&h; lo = *(uint32_t*)&l;
}
__device__ __forceinline__ float qred_max(float v) {
    v = fmaxf(v, __shfl_xor_sync(~0u, v, 1));
    return fmaxf(v, __shfl_xor_sync(~0u, v, 2));
}
__device__ __forceinline__ float qred_sum(float v) {
    v += __shfl_xor_sync(~0u, v, 1);
    return v + __shfl_xor_sync(~0u, v, 2);
}

// ---------------------------------------------------------------------------
// Fused conversion kernel (one launch):
//  blocks [0,1024):    x fp32 -> g_xh/g_xl
//  blocks [1024,4096): W_attn [1024,3072] -> g_wh [3072][1024] (fp16 hi)
//  blocks [4096,5120): W_proj [1024,1024] -> g_ph [1024][1024]
// ---------------------------------------------------------------------------
__global__ __launch_bounds__(256)
void convert_all(const float* __restrict__ x,
                 const float* __restrict__ Wattn,
                 const float* __restrict__ Wproj)
{
    const int blk = blockIdx.x;
    if (blk < 1024) {
        const size_t n4 = (size_t)BT_ * KDIM / 4;
        for (size_t i = (size_t)blk * 256 + threadIdx.x; i < n4; i += (size_t)1024 * 256) {
            float4 v = ((const float4*)x)[i];
            uint32_t h0, l0, h1, l1;
            packsplit(v.x, v.y, h0, l0);
            packsplit(v.z, v.w, h1, l1);
            ((uint32_t*)g_xh)[2 * i] = h0; ((uint32_t*)g_xh)[2 * i + 1] = h1;
            ((uint32_t*)g_xl)[2 * i] = l0; ((uint32_t*)g_xl)[2 * i + 1] = l1;
        }
    } else {
        const int W = (blk < 4096) ? 0 : 1;
        const int bidx = W ? (blk - 4096) : (blk - 1024);
        const int NBX = W ? 32 : 96;
        const int NC = W ? C_ : 3 * C_;
        const float* src = W ? Wproj : Wattn;
        __half* dh = W ? g_ph : g_wh;
        const int bx = bidx % NBX;
        const int by = bidx / NBX;
        const int tx = threadIdx.x & 31;
        const int ty = threadIdx.x >> 5;
        __shared__ float tile[32][33];
        const int xcol = bx * 32 + tx;
        const int y0 = by * 32;
#pragma unroll
        for (int j = 0; j < 32; j += 8)
            tile[ty + j][tx] = src[(size_t)(y0 + ty + j) * NC + xcol];
        __syncthreads();
        const int ox = y0 + tx;
        const int oyb = bx * 32;
#pragma unroll
        for (int j = 0; j < 32; j += 8)
            dh[(size_t)(oyb + ty + j) * KDIM + ox] = __float2half(tile[tx][ty + j]);
    }
}

// ---------------------------------------------------------------------------
// fp16x2 GEMM via mma.sync (R8 config — best measured): D = A x B^T.
// CTA tile 128x128, warp tile 32x64 (4M x 2N), K_chunk=64, 2-stage, 2 CTAs/SM.
// Stage (48KB): [Ah 16K][Al 16K][Bh 16K], SW128.
// ---------------------------------------------------------------------------
#define SM_STAGE 49152
#define SMEM_GEMM_BYTES 98304    // 2 stages

template <int MODE>
__global__ __launch_bounds__(256, 2)
void mma_gemm(const float* __restrict__ bias,
              float* __restrict__ o0, float* __restrict__ o1, float* __restrict__ o2)
{
    extern __shared__ __align__(1024) char smem[];
    const uint32_t sm = s2u(smem);
    const int tid = threadIdx.x;
    const int wid = tid >> 5;
    const int lid = tid & 31;
    const int n0 = blockIdx.x * 128;
    const int m0 = blockIdx.y * 128;

    const __half* Ahp = (MODE == 0) ? g_xh : g_ah;
    const __half* Alp = (MODE == 0) ? g_xl : g_al;
    const __half* Bhp = (MODE == 0) ? g_wh : g_ph;

    // copy plan: 3072 x 16B per stage, 12 per thread
    auto issue_loads = [&](int c, int s) {
        const uint32_t sb = sm + (uint32_t)s * SM_STAGE;
#pragma unroll
        for (int r = 0; r < 12; r++) {
            const int id = tid + r * 256;
            const int row = (id >> 3) & 127;
            const int c16 = id & 7;
            const uint32_t off = swz((uint32_t)(row * 128 + c16 * 16));
            if (id < 1024)
                cp_async16(sb + off, Ahp + (size_t)(m0 + row) * KDIM + c * 64 + c16 * 8);
            else if (id < 2048)
                cp_async16(sb + 16384 + off, Alp + (size_t)(m0 + row) * KDIM + c * 64 + c16 * 8);
            else
                cp_async16(sb + 32768 + off, Bhp + (size_t)(n0 + row) * KDIM + c * 64 + c16 * 8);
        }
        asm volatile("cp.async.commit_group;" ::: "memory");
    };

    const int wm = (wid & 3) * 32;       // warp M origin (4 rows of warps)
    const int wn = (wid >> 2) * 64;      // warp N origin (2 cols of warps)
    const int g = lid >> 2;
    const int tig = lid & 3;
    const int aRow = lid & 15;
    const int aKb = (lid >> 4) * 16;
    const int bRow = ((lid >> 4) & 1) * 8 + (lid & 7);
    const int bKb = ((lid >> 3) & 1) * 16;

    float Cr[2][8][4];                   // [mi][n8 slice][quad]
#pragma unroll
    for (int mi = 0; mi < 2; mi++)
#pragma unroll
        for (int j = 0; j < 8; j++)
#pragma unroll
            for (int qi = 0; qi < 4; qi++) Cr[mi][j][qi] = 0.f;

    issue_loads(0, 0);
    issue_loads(1, 1);

    for (int c = 0; c < 16; c++) {
        const int s = c & 1;
        if (c < 15) asm volatile("cp.async.wait_group 1;" ::: "memory");
        else        asm volatile("cp.async.wait_group 0;" ::: "memory");
        __syncthreads();

        const uint32_t sb = sm + (uint32_t)s * SM_STAGE;
        const uint32_t tAh = sb, tAl = sb + 16384, tBh = sb + 32768;

#pragma unroll
        for (int ks = 0; ks < 4; ks++) {
            const int kb = ks * 32;
            uint32_t ah[2][4], al[2][4], bh[4][4];
#pragma unroll
            for (int mi = 0; mi < 2; mi++) {
                const uint32_t off = swz((uint32_t)((wm + mi * 16 + aRow) * 128 + kb + aKb));
                ldsm4(ah[mi], tAh + off);
                ldsm4(al[mi], tAl + off);
            }
#pragma unroll
            for (int jp = 0; jp < 4; jp++) {
                const uint32_t off = swz((uint32_t)((wn + jp * 16 + bRow) * 128 + kb + bKb));
                ldsm4(bh[jp], tBh + off);
            }
#pragma unroll
            for (int mi = 0; mi < 2; mi++)
#pragma unroll
                for (int j = 0; j < 8; j++) {
                    const int jp = j >> 1, o = (j & 1) * 2;
                    mma2(Cr[mi][j], ah[mi], bh[jp][o], bh[jp][o + 1]);
                    mma2(Cr[mi][j], al[mi], bh[jp][o], bh[jp][o + 1]);
                }
        }
        __syncthreads();              // all smem reads of stage s done
        if (c + 2 < 16) issue_loads(c + 2, s);
    }

    // ---- epilogue ----
#pragma unroll
    for (int mi = 0; mi < 2; mi++)
#pragma unroll
        for (int j = 0; j < 8; j++) {
            const int col = n0 + wn + (j >> 1) * 16 + (j & 1) * 8 + tig * 2;
            const float2 bb = *(const float2*)(bias + col);
#pragma unroll
            for (int half = 0; half < 2; half++) {
                const int row = m0 + wm + mi * 16 + g + half * 8;
                float2 v;
                v.x = Cr[mi][j][half * 2 + 0] + bb.x;
                v.y = Cr[mi][j][half * 2 + 1] + bb.y;
                if (MODE == 0) {
                    const int seg = col >> 10;
                    const int c0 = col & 1023;
                    const int h = c0 >> 6;
                    const int dd = c0 & 63;
                    const int b = row >> 11;
                    const int t = row & (T_ - 1);
                    const size_t idx = ((size_t)(b * H_ + h) * T_ + t) * D_ + dd;
                    if (seg == 0) {
                        *(uint32_t*)&g_qh[idx] = packh2(v.x * QSCALE, v.y * QSCALE);
                    } else if (seg == 1) {
                        *(float2*)&o1[idx] = v;
                        *(uint32_t*)&g_kh[idx] = packh2(v.x, v.y);
                    } else {
                        *(float2*)&o2[idx] = v;
                        *(uint32_t*)&g_vh[idx] = packh2(v.x, v.y);
                    }
                } else {
                    *(float2*)&o0[(size_t)row * C_ + col] = v;
                }
            }
        }
}

// ---------------------------------------------------------------------------
// Flash attention via mma.sync fp16; Q single-term (fp16), P split hi/lo.
// 3-stage KV (single sync per tile), 2 CTAs/SM.
// smem: Q 16KB @0; stage s @16384+s*16384: [Kh 8KB][Vh 8KB]
// ---------------------------------------------------------------------------
#define AT_SMEM 65536            // Q 16K + 3 stages x 16K

__global__ __launch_bounds__(256, 2)
void attn_mma()
{
    extern __shared__ __align__(1024) char smem[];
    const uint32_t sm = s2u(smem);
    const int tid = threadIdx.x;
    const int wid = tid >> 5;
    const int lid = tid & 31;
    const int qb = 15 - blockIdx.x;          // heavy CTAs first
    const int bh = blockIdx.y;
    const size_t base_qkv = (size_t)bh * T_ * D_;
    const int nt = 2 * qb + 2;

    // Q loads (folded into group 0): 1024 x 16B
#pragma unroll
    for (int r = 0; r < 4; r++) {
        const int id = tid + r * 256;
        const int row = id >> 3;
        const int c16 = id & 7;
        const uint32_t dst = sm + swz((uint32_t)(row * 128 + c16 * 16));
        const __half* src = g_qh + base_qkv + (size_t)(qb * 128 + row) * D_ + c16 * 8;
        cp_async16(dst, src);
    }
    auto issue_kv = [&](int kt, int s) {
        const uint32_t sb = sm + 16384 + (uint32_t)s * 16384;
#pragma unroll
        for (int r = 0; r < 4; r++) {
            const int id = tid + r * 256;
            const int bsel = id >> 9;        // 0 Kh 1 Vh
            const int row = (id >> 3) & 63;
            const int c16 = id & 7;
            const uint32_t dst = sb + bsel * 8192 + swz((uint32_t)(row * 128 + c16 * 16));
            const __half* src = (bsel ? g_vh : g_kh) + base_qkv
                                + (size_t)(kt * 64 + row) * D_ + c16 * 8;
            cp_async16(dst, src);
        }
        asm volatile("cp.async.commit_group;" ::: "memory");
    };
    issue_kv(0, 0);
    issue_kv(1, 1);

    const int g = lid >> 2;
    const int t2 = (lid & 3) * 2;
    const int lrow16 = lid & 15;
    const int lhi = (lid >> 4) * 16;

    uint32_t qh[4][4];
    float cfr[8][4], ofr[8][4];
    float mrow0 = -1e30f, mrow1 = -1e30f, lrow0 = 0.f, lrow1 = 0.f;
#pragma unroll
    for (int j = 0; j < 8; j++)
#pragma unroll
        for (int qi = 0; qi < 4; qi++) ofr[j][qi] = 0.f;

    for (int kb = 0; kb < nt; kb++) {
        const int s = kb % 3;
        if (kb + 1 < nt) asm volatile("cp.async.wait_group 1;" ::: "memory");
        else             asm volatile("cp.async.wait_group 0;" ::: "memory");
        __syncthreads();
        // stage (kb+2)%3 == (kb-1)%3; its reads finished before this sync
        if (kb + 2 < nt) issue_kv(kb + 2, (kb + 2) % 3);
        if (kb == 0) {
#pragma unroll
            for (int kc = 0; kc < 4; kc++) {
                const uint32_t off = swz((uint32_t)((wid * 16 + lrow16) * 128 + kc * 32 + lhi));
                ldsm4(qh[kc], sm + off);
            }
        }
        const uint32_t kvb = sm + 16384 + (uint32_t)s * 16384;

        // ---- S = Q K^T (Q single fp16; pipelined K frags) ----
#pragma unroll
        for (int j = 0; j < 8; j++)
#pragma unroll
            for (int qi = 0; qi < 4; qi++) cfr[j][qi] = 0.f;
#pragma unroll
        for (int kc = 0; kc < 4; kc++) {
            uint32_t khb[2][4];
            auto LK = [&](int jp, int bp) {
                const uint32_t off = swz((uint32_t)((jp * 16 + lrow16) * 128 + kc * 32 + lhi));
                ldsm4(khb[bp], kvb + off);
            };
            auto MS = [&](int jp, int bp) {
                mma2(cfr[2 * jp],     qh[kc], khb[bp][0], khb[bp][2]);
                mma2(cfr[2 * jp + 1], qh[kc], khb[bp][1], khb[bp][3]);
            };
            LK(0, 0); LK(1, 1);
            MS(0, 0); LK(2, 0);
            MS(1, 1); LK(3, 1);
            MS(2, 0);
            MS(3, 1);
        }

        // ---- causal mask (diagonal tiles only) ----
        if (kb >= 2 * qb) {
            const int qr = qb * 128 + wid * 16 + g;
            const int kv0 = kb * 64;
#pragma unroll
            for (int j = 0; j < 8; j++) {
                const int col = kv0 + j * 8 + t2;
#pragma unroll
                for (int qi = 0; qi < 4; qi++) {
                    const int row = qr + ((qi >> 1) << 3);
                    if (col + (qi & 1) > row) cfr[j][qi] = -1e30f;
                }
            }
        }

        // ---- online softmax (log2 domain) ----
        float mx0 = -1e30f, mx1 = -1e30f;
#pragma unroll
        for (int j = 0; j < 8; j++) {
            mx0 = fmaxf(mx0, fmaxf(cfr[j][0], cfr[j][1]));
            mx1 = fmaxf(mx1, fmaxf(cfr[j][2], cfr[j][3]));
        }
        mx0 = qred_max(mx0);
        mx1 = qred_max(mx1);
        const float mn0 = fmaxf(mrow0, mx0), mn1 = fmaxf(mrow1, mx1);
        const float al0 = exp2f(mrow0 - mn0), al1 = exp2f(mrow1 - mn1);
        mrow0 = mn0; mrow1 = mn1;
        float s0 = 0.f, s1 = 0.f;
#pragma unroll
        for (int j = 0; j < 8; j++) {
            cfr[j][0] = exp2f(cfr[j][0] - mn0);
            cfr[j][1] = exp2f(cfr[j][1] - mn0);
            cfr[j][2] = exp2f(cfr[j][2] - mn1);
            cfr[j][3] = exp2f(cfr[j][3] - mn1);
            s0 += cfr[j][0] + cfr[j][1];
            s1 += cfr[j][2] + cfr[j][3];
        }
        s0 = qred_sum(s0);
        s1 = qred_sum(s1);
        lrow0 = lrow0 * al0 + s0;
        lrow1 = lrow1 * al1 + s1;
#pragma unroll
        for (int j = 0; j < 8; j++) {
            ofr[j][0] *= al0; ofr[j][1] *= al0;
            ofr[j][2] *= al1; ofr[j][3] *= al1;
        }

        // ---- O += P V (P split hi/lo; pipelined V frags) ----
#pragma unroll
        for (int kc = 0; kc < 4; kc++) {
            uint32_t ph[4], pl[4];
            packsplit(cfr[2 * kc][0],     cfr[2 * kc][1],     ph[0], pl[0]);
            packsplit(cfr[2 * kc][2],     cfr[2 * kc][3],     ph[1], pl[1]);
            packsplit(cfr[2 * kc + 1][0], cfr[2 * kc + 1][1], ph[2], pl[2]);
            packsplit(cfr[2 * kc + 1][2], cfr[2 * kc + 1][3], ph[3], pl[3]);
            uint32_t vb[2][4];
            auto LV = [&](int nc, int bp) {
                const uint32_t off = swz((uint32_t)((kc * 16 + lrow16) * 128 + nc * 32 + lhi));
                ldsm4t(vb[bp], kvb + 8192 + off);
            };
            auto MV = [&](int nc, int bp) {
                mma2(ofr[2 * nc],     ph, vb[bp][0], vb[bp][1]);
                mma2(ofr[2 * nc],     pl, vb[bp][0], vb[bp][1]);
                mma2(ofr[2 * nc + 1], ph, vb[bp][2], vb[bp][3]);
                mma2(ofr[2 * nc + 1], pl, vb[bp][2], vb[bp][3]);
            };
            LV(0, 0); LV(1, 1);
            MV(0, 0); LV(2, 0);
            MV(1, 1); LV(3, 1);
            MV(2, 0);
            MV(3, 1);
        }
    }

    // ---- epilogue: write hi/lo fp16 into [B,T,C] for proj GEMM ----
    const float inv0 = 1.f / lrow0, inv1 = 1.f / lrow1;
    const int b = bh >> 4, h = bh & 15;
    const int t0 = qb * 128 + wid * 16 + g;
#pragma unroll
    for (int j = 0; j < 8; j++) {
        const int d = j * 8 + t2;
        const size_t i0 = ((size_t)(b * T_ + t0)) * C_ + h * 64 + d;
        const size_t i1 = i0 + (size_t)8 * C_;
        uint32_t hi, lo;
        packsplit(ofr[j][0] * inv0, ofr[j][1] * inv0, hi, lo);
        *(uint32_t*)&g_ah[i0] = hi;
        *(uint32_t*)&g_al[i0] = lo;
        packsplit(ofr[j][2] * inv1, ofr[j][3] * inv1, hi, lo);
        *(uint32_t*)&g_ah[i1] = hi;
        *(uint32_t*)&g_al[i1] = lo;
    }
}

// ---------------------------------------------------------------------------
// Launch. Inputs: x, mask, W_attn, b_attn, W_proj, b_proj.
// Output: [out (B,T,C) | k (B,H,T,D) | v (B,H,T,D)] fp32.
// ---------------------------------------------------------------------------
extern "C" void kernel_launch(void* const* d_in, const int* in_sizes, int n_in,
                              void* d_out, int out_size)
{
    (void)in_sizes; (void)n_in; (void)out_size;
    const float* x      = (const float*)d_in[0];
    const float* W_attn = (const float*)d_in[2];
    const float* b_attn = (const float*)d_in[3];
    const float* W_proj = (const float*)d_in[4];
    const float* b_proj = (const float*)d_in[5];

    float* out  = (float*)d_out;
    float* kout = out + (size_t)B_ * H_ * T_ * D_;
    float* vout = kout + (size_t)B_ * H_ * T_ * D_;

    cudaFuncSetAttribute(mma_gemm<0>, cudaFuncAttributeMaxDynamicSharedMemorySize,
                         SMEM_GEMM_BYTES);
    cudaFuncSetAttribute(mma_gemm<1>, cudaFuncAttributeMaxDynamicSharedMemorySize,
                         SMEM_GEMM_BYTES);
    cudaFuncSetAttribute(attn_mma, cudaFuncAttributeMaxDynamicSharedMemorySize,
                         AT_SMEM);

    // 1) fused conversions (x split + both weight transposes)
    convert_all<<<5120, 256>>>(x, W_attn, W_proj);

    // 2) QKV GEMM + bias + scatter (tile 128x128 -> grid 24x64)
    mma_gemm<0><<<dim3(24, 64), 256, SMEM_GEMM_BYTES>>>(b_attn, nullptr, kout, vout);

    // 3) causal flash attention (tensor cores) -> g_ah/g_al
    attn_mma<<<dim3(16, 64), 256, AT_SMEM>>>();

    // 4) proj GEMM (grid 8x64)
    mma_gemm<1><<<dim3(8, 64), 256, SMEM_GEMM_BYTES>>>(b_proj, out, nullptr, nullptr);
}

// round 11
// speedup vs baseline: 1.7370x; 1.5458x over previous
#include <cuda_runtime.h>
#include <cuda_fp16.h>
#include <cstdint>

// Problem constants
#define B_ 4
#define T_ 2048
#define C_ 1024
#define H_ 16
#define D_ 64
#define BT_ (B_ * T_)            // 8192
#define KDIM 1024

#define QSCALE 0.18033688011112042f   // 0.125 * log2(e)

// ---------------------------------------------------------------------------
// Scratch (device globals). ALL operands single-term fp16 now.
// ---------------------------------------------------------------------------
__device__ __half g_x[(size_t)BT_ * KDIM];     // x fp16 [B,T,C]
__device__ __half g_w[(size_t)3 * C_ * KDIM];  // W_attn^T [3072][1024]
__device__ __half g_p[(size_t)C_ * KDIM];      // W_proj^T [1024][1024]
__device__ __half g_a[(size_t)BT_ * KDIM];     // attn-out fp16 [B,T,C]
// Q (pre-scaled by QSCALE), K, V fp16 in [B,H,T,D]
__device__ __half g_q[(size_t)BT_ * C_];
__device__ __half g_k[(size_t)BT_ * C_];
__device__ __half g_v[(size_t)BT_ * C_];

// ---------------------------------------------------------------------------
// helpers (sm_80-era PTX — legal at compute_103 base)
// ---------------------------------------------------------------------------
__device__ __forceinline__ uint32_t s2u(const void* p) {
    uint32_t a;
    asm("{ .reg .u64 t; cvta.to.shared.u64 t, %1; cvt.u32.u64 %0, t; }" : "=r"(a) : "l"(p));
    return a;
}
__device__ __forceinline__ uint32_t swz(uint32_t off) {   // SW128
    return off ^ ((off >> 3) & 0x70);
}
__device__ __forceinline__ void cp_async16(uint32_t dst, const void* src) {
    asm volatile("cp.async.cg.shared.global [%0], [%1], 16;" :: "r"(dst), "l"(src) : "memory");
}
__device__ __forceinline__ void ldsm4(uint32_t* r, uint32_t addr) {
    asm volatile("ldmatrix.sync.aligned.m8n8.x4.shared.b16 {%0,%1,%2,%3}, [%4];"
                 : "=r"(r[0]), "=r"(r[1]), "=r"(r[2]), "=r"(r[3]) : "r"(addr));
}
__device__ __forceinline__ void ldsm4t(uint32_t* r, uint32_t addr) {
    asm volatile("ldmatrix.sync.aligned.m8n8.x4.trans.shared.b16 {%0,%1,%2,%3}, [%4];"
                 : "=r"(r[0]), "=r"(r[1]), "=r"(r[2]), "=r"(r[3]) : "r"(addr));
}
__device__ __forceinline__ void mma2(float* c, const uint32_t* a, uint32_t b0, uint32_t b1) {
    asm volatile(
        "mma.sync.aligned.m16n8k16.row.col.f32.f16.f16.f32 "
        "{%0,%1,%2,%3}, {%4,%5,%6,%7}, {%8,%9}, {%0,%1,%2,%3};"
        : "+f"(c[0]), "+f"(c[1]), "+f"(c[2]), "+f"(c[3])
        : "r"(a[0]), "r"(a[1]), "r"(a[2]), "r"(a[3]), "r"(b0), "r"(b1));
}
__device__ __forceinline__ uint32_t packh2(float x, float y) {
    __half2 t; t.x = __float2half(x); t.y = __float2half(y);
    return *(uint32_t*)&t;
}
__device__ __forceinline__ float qred_max(float v) {
    v = fmaxf(v, __shfl_xor_sync(~0u, v, 1));
    return fmaxf(v, __shfl_xor_sync(~0u, v, 2));
}
__device__ __forceinline__ float qred_sum(float v) {
    v += __shfl_xor_sync(~0u, v, 1);
    return v + __shfl_xor_sync(~0u, v, 2);
}

// ---------------------------------------------------------------------------
// Fused conversion kernel (one launch):
//  blocks [0,1024):    x fp32 -> g_x (fp16)
//  blocks [1024,4096): W_attn [1024,3072] -> g_w [3072][1024]
//  blocks [4096,5120): W_proj [1024,1024] -> g_p [1024][1024]
// ---------------------------------------------------------------------------
__global__ __launch_bounds__(256)
void convert_all(const float* __restrict__ x,
                 const float* __restrict__ Wattn,
                 const float* __restrict__ Wproj)
{
    const int blk = blockIdx.x;
    if (blk < 1024) {
        const size_t n4 = (size_t)BT_ * KDIM / 4;
        for (size_t i = (size_t)blk * 256 + threadIdx.x; i < n4; i += (size_t)1024 * 256) {
            float4 v = ((const float4*)x)[i];
            ((uint32_t*)g_x)[2 * i]     = packh2(v.x, v.y);
            ((uint32_t*)g_x)[2 * i + 1] = packh2(v.z, v.w);
        }
    } else {
        const int W = (blk < 4096) ? 0 : 1;
        const int bidx = W ? (blk - 4096) : (blk - 1024);
        const int NBX = W ? 32 : 96;
        const int NC = W ? C_ : 3 * C_;
        const float* src = W ? Wproj : Wattn;
        __half* dh = W ? g_p : g_w;
        const int bx = bidx % NBX;
        const int by = bidx / NBX;
        const int tx = threadIdx.x & 31;
        const int ty = threadIdx.x >> 5;
        __shared__ float tile[32][33];
        const int xcol = bx * 32 + tx;
        const int y0 = by * 32;
#pragma unroll
        for (int j = 0; j < 32; j += 8)
            tile[ty + j][tx] = src[(size_t)(y0 + ty + j) * NC + xcol];
        __syncthreads();
        const int ox = y0 + tx;
        const int oyb = bx * 32;
#pragma unroll
        for (int j = 0; j < 32; j += 8)
            dh[(size_t)(oyb + ty + j) * KDIM + ox] = __float2half(tile[tx][ty + j]);
    }
}

// ---------------------------------------------------------------------------
// Plain fp16 GEMM via mma.sync: D = A x B^T (both single-term).
// CTA tile 128x128, warp tile 32x64 (4M x 2N), K_chunk=64,
// 3-stage ring with ONE syncthreads per chunk, 2 CTAs/SM.
// Stage (32KB): [A 16K][B 16K], SW128.
// ---------------------------------------------------------------------------
#define SM_STAGE 32768
#define SMEM_GEMM_BYTES 98304    // 3 stages
#define NCH 16                   // 1024 / 64

template <int MODE>
__global__ __launch_bounds__(256, 2)
void mma_gemm(const float* __restrict__ bias,
              float* __restrict__ o0, float* __restrict__ o1, float* __restrict__ o2)
{
    extern __shared__ __align__(1024) char smem[];
    const uint32_t sm = s2u(smem);
    const int tid = threadIdx.x;
    const int wid = tid >> 5;
    const int lid = tid & 31;
    const int n0 = blockIdx.x * 128;
    const int m0 = blockIdx.y * 128;

    const __half* Ap = (MODE == 0) ? g_x : g_a;
    const __half* Bp = (MODE == 0) ? g_w : g_p;

    // copy plan: 2048 x 16B per stage, 8 per thread
    auto issue_loads = [&](int c, int s) {
        const uint32_t sb = sm + (uint32_t)s * SM_STAGE;
#pragma unroll
        for (int r = 0; r < 8; r++) {
            const int id = tid + r * 256;
            const int row = (id >> 3) & 127;
            const int c16 = id & 7;
            const uint32_t off = swz((uint32_t)(row * 128 + c16 * 16));
            if (id < 1024)
                cp_async16(sb + off, Ap + (size_t)(m0 + row) * KDIM + c * 64 + c16 * 8);
            else
                cp_async16(sb + 16384 + off, Bp + (size_t)(n0 + row) * KDIM + c * 64 + c16 * 8);
        }
        asm volatile("cp.async.commit_group;" ::: "memory");
    };

    const int wm = (wid & 3) * 32;       // warp M origin (4 rows of warps)
    const int wn = (wid >> 2) * 64;      // warp N origin (2 cols of warps)
    const int g = lid >> 2;
    const int tig = lid & 3;
    const int aRow = lid & 15;
    const int aKb = (lid >> 4) * 16;
    const int bRow = ((lid >> 4) & 1) * 8 + (lid & 7);
    const int bKb = ((lid >> 3) & 1) * 16;

    float Cr[2][8][4];                   // [mi][n8 slice][quad]
#pragma unroll
    for (int mi = 0; mi < 2; mi++)
#pragma unroll
        for (int j = 0; j < 8; j++)
#pragma unroll
            for (int qi = 0; qi < 4; qi++) Cr[mi][j][qi] = 0.f;

    issue_loads(0, 0);
    issue_loads(1, 1);

    for (int c = 0; c < NCH; c++) {
        const int s = c % 3;
        if (c < NCH - 1) asm volatile("cp.async.wait_group 1;" ::: "memory");
        else             asm volatile("cp.async.wait_group 0;" ::: "memory");
        __syncthreads();
        // stage (c+2)%3 == (c-1)%3: fully consumed before this sync
        if (c + 2 < NCH) issue_loads(c + 2, (c + 2) % 3);

        const uint32_t sb = sm + (uint32_t)s * SM_STAGE;
        const uint32_t tA = sb, tB = sb + 16384;

#pragma unroll
        for (int ks = 0; ks < 4; ks++) {
            const int kb = ks * 32;
            uint32_t af[2][4], bf[4][4];
#pragma unroll
            for (int mi = 0; mi < 2; mi++) {
                const uint32_t off = swz((uint32_t)((wm + mi * 16 + aRow) * 128 + kb + aKb));
                ldsm4(af[mi], tA + off);
            }
#pragma unroll
            for (int jp = 0; jp < 4; jp++) {
                const uint32_t off = swz((uint32_t)((wn + jp * 16 + bRow) * 128 + kb + bKb));
                ldsm4(bf[jp], tB + off);
            }
#pragma unroll
            for (int mi = 0; mi < 2; mi++)
#pragma unroll
                for (int j = 0; j < 8; j++) {
                    const int jp = j >> 1, o = (j & 1) * 2;
                    mma2(Cr[mi][j], af[mi], bf[jp][o], bf[jp][o + 1]);
                }
        }
    }

    // ---- epilogue ----
#pragma unroll
    for (int mi = 0; mi < 2; mi++)
#pragma unroll
        for (int j = 0; j < 8; j++) {
            const int col = n0 + wn + (j >> 1) * 16 + (j & 1) * 8 + tig * 2;
            const float2 bb = *(const float2*)(bias + col);
#pragma unroll
            for (int half = 0; half < 2; half++) {
                const int row = m0 + wm + mi * 16 + g + half * 8;
                float2 v;
                v.x = Cr[mi][j][half * 2 + 0] + bb.x;
                v.y = Cr[mi][j][half * 2 + 1] + bb.y;
                if (MODE == 0) {
                    const int seg = col >> 10;
                    const int c0 = col & 1023;
                    const int h = c0 >> 6;
                    const int dd = c0 & 63;
                    const int b = row >> 11;
                    const int t = row & (T_ - 1);
                    const size_t idx = ((size_t)(b * H_ + h) * T_ + t) * D_ + dd;
                    if (seg == 0) {
                        *(uint32_t*)&g_q[idx] = packh2(v.x * QSCALE, v.y * QSCALE);
                    } else if (seg == 1) {
                        *(float2*)&o1[idx] = v;
                        *(uint32_t*)&g_k[idx] = packh2(v.x, v.y);
                    } else {
                        *(float2*)&o2[idx] = v;
                        *(uint32_t*)&g_v[idx] = packh2(v.x, v.y);
                    }
                } else {
                    *(float2*)&o0[(size_t)row * C_ + col] = v;
                }
            }
        }
}

// ---------------------------------------------------------------------------
// Flash attention via mma.sync fp16; Q, K, V, P all single-term.
// 3-stage KV (single sync per tile), 2 CTAs/SM.
// smem: Q 16KB @0; stage s @16384+s*16384: [K 8KB][V 8KB]
// ---------------------------------------------------------------------------
#define AT_SMEM 65536            // Q 16K + 3 stages x 16K

__global__ __launch_bounds__(256, 2)
void attn_mma()
{
    extern __shared__ __align__(1024) char smem[];
    const uint32_t sm = s2u(smem);
    const int tid = threadIdx.x;
    const int wid = tid >> 5;
    const int lid = tid & 31;
    const int qb = 15 - blockIdx.x;          // heavy CTAs first
    const int bh = blockIdx.y;
    const size_t base_qkv = (size_t)bh * T_ * D_;
    const int nt = 2 * qb + 2;

    // Q loads (folded into group 0): 1024 x 16B
#pragma unroll
    for (int r = 0; r < 4; r++) {
        const int id = tid + r * 256;
        const int row = id >> 3;
        const int c16 = id & 7;
        const uint32_t dst = sm + swz((uint32_t)(row * 128 + c16 * 16));
        const __half* src = g_q + base_qkv + (size_t)(qb * 128 + row) * D_ + c16 * 8;
        cp_async16(dst, src);
    }
    auto issue_kv = [&](int kt, int s) {
        const uint32_t sb = sm + 16384 + (uint32_t)s * 16384;
#pragma unroll
        for (int r = 0; r < 4; r++) {
            const int id = tid + r * 256;
            const int bsel = id >> 9;        // 0 K 1 V
            const int row = (id >> 3) & 63;
            const int c16 = id & 7;
            const uint32_t dst = sb + bsel * 8192 + swz((uint32_t)(row * 128 + c16 * 16));
            const __half* src = (bsel ? g_v : g_k) + base_qkv
                                + (size_t)(kt * 64 + row) * D_ + c16 * 8;
            cp_async16(dst, src);
        }
        asm volatile("cp.async.commit_group;" ::: "memory");
    };
    issue_kv(0, 0);
    issue_kv(1, 1);

    const int g = lid >> 2;
    const int t2 = (lid & 3) * 2;
    const int lrow16 = lid & 15;
    const int lhi = (lid >> 4) * 16;

    uint32_t qh[4][4];
    float cfr[8][4], ofr[8][4];
    float mrow0 = -1e30f, mrow1 = -1e30f, lrow0 = 0.f, lrow1 = 0.f;
#pragma unroll
    for (int j = 0; j < 8; j++)
#pragma unroll
        for (int qi = 0; qi < 4; qi++) ofr[j][qi] = 0.f;

    for (int kb = 0; kb < nt; kb++) {
        const int s = kb % 3;
        if (kb + 1 < nt) asm volatile("cp.async.wait_group 1;" ::: "memory");
        else             asm volatile("cp.async.wait_group 0;" ::: "memory");
        __syncthreads();
        // stage (kb+2)%3 == (kb-1)%3; its reads finished before this sync
        if (kb + 2 < nt) issue_kv(kb + 2, (kb + 2) % 3);
        if (kb == 0) {
#pragma unroll
            for (int kc = 0; kc < 4; kc++) {
                const uint32_t off = swz((uint32_t)((wid * 16 + lrow16) * 128 + kc * 32 + lhi));
                ldsm4(qh[kc], sm + off);
            }
        }
        const uint32_t kvb = sm + 16384 + (uint32_t)s * 16384;

        // ---- S = Q K^T (single-term; pipelined K frags) ----
#pragma unroll
        for (int j = 0; j < 8; j++)
#pragma unroll
            for (int qi = 0; qi < 4; qi++) cfr[j][qi] = 0.f;
#pragma unroll
        for (int kc = 0; kc < 4; kc++) {
            uint32_t khb[2][4];
            auto LK = [&](int jp, int bp) {
                const uint32_t off = swz((uint32_t)((jp * 16 + lrow16) * 128 + kc * 32 + lhi));
                ldsm4(khb[bp], kvb + off);
            };
            auto MS = [&](int jp, int bp) {
                mma2(cfr[2 * jp],     qh[kc], khb[bp][0], khb[bp][2]);
                mma2(cfr[2 * jp + 1], qh[kc], khb[bp][1], khb[bp][3]);
            };
            LK(0, 0); LK(1, 1);
            MS(0, 0); LK(2, 0);
            MS(1, 1); LK(3, 1);
            MS(2, 0);
            MS(3, 1);
        }

        // ---- causal mask (diagonal tiles only) ----
        if (kb >= 2 * qb) {
            const int qr = qb * 128 + wid * 16 + g;
            const int kv0 = kb * 64;
#pragma unroll
            for (int j = 0; j < 8; j++) {
                const int col = kv0 + j * 8 + t2;
#pragma unroll
                for (int qi = 0; qi < 4; qi++) {
                    const int row = qr + ((qi >> 1) << 3);
                    if (col + (qi & 1) > row) cfr[j][qi] = -1e30f;
                }
            }
        }

        // ---- online softmax (log2 domain) ----
        float mx0 = -1e30f, mx1 = -1e30f;
#pragma unroll
        for (int j = 0; j < 8; j++) {
            mx0 = fmaxf(mx0, fmaxf(cfr[j][0], cfr[j][1]));
            mx1 = fmaxf(mx1, fmaxf(cfr[j][2], cfr[j][3]));
        }
        mx0 = qred_max(mx0);
        mx1 = qred_max(mx1);
        const float mn0 = fmaxf(mrow0, mx0), mn1 = fmaxf(mrow1, mx1);
        const float al0 = exp2f(mrow0 - mn0), al1 = exp2f(mrow1 - mn1);
        mrow0 = mn0; mrow1 = mn1;
        float s0 = 0.f, s1 = 0.f;
#pragma unroll
        for (int j = 0; j < 8; j++) {
            cfr[j][0] = exp2f(cfr[j][0] - mn0);
            cfr[j][1] = exp2f(cfr[j][1] - mn0);
            cfr[j][2] = exp2f(cfr[j][2] - mn1);
            cfr[j][3] = exp2f(cfr[j][3] - mn1);
            s0 += cfr[j][0] + cfr[j][1];
            s1 += cfr[j][2] + cfr[j][3];
        }
        s0 = qred_sum(s0);
        s1 = qred_sum(s1);
        lrow0 = lrow0 * al0 + s0;
        lrow1 = lrow1 * al1 + s1;
#pragma unroll
        for (int j = 0; j < 8; j++) {
            ofr[j][0] *= al0; ofr[j][1] *= al0;
            ofr[j][2] *= al1; ofr[j][3] *= al1;
        }

        // ---- O += P V (P single fp16; pipelined V frags) ----
#pragma unroll
        for (int kc = 0; kc < 4; kc++) {
            uint32_t ph[4];
            ph[0] = packh2(cfr[2 * kc][0],     cfr[2 * kc][1]);
            ph[1] = packh2(cfr[2 * kc][2],     cfr[2 * kc][3]);
            ph[2] = packh2(cfr[2 * kc + 1][0], cfr[2 * kc + 1][1]);
            ph[3] = packh2(cfr[2 * kc + 1][2], cfr[2 * kc + 1][3]);
            uint32_t vb[2][4];
            auto LV = [&](int nc, int bp) {
                const uint32_t off = swz((uint32_t)((kc * 16 + lrow16) * 128 + nc * 32 + lhi));
                ldsm4t(vb[bp], kvb + 8192 + off);
            };
            auto MV = [&](int nc, int bp) {
                mma2(ofr[2 * nc],     ph, vb[bp][0], vb[bp][1]);
                mma2(ofr[2 * nc + 1], ph, vb[bp][2], vb[bp][3]);
            };
            LV(0, 0); LV(1, 1);
            MV(0, 0); LV(2, 0);
            MV(1, 1); LV(3, 1);
            MV(2, 0);
            MV(3, 1);
        }
    }

    // ---- epilogue: write fp16 into [B,T,C] for proj GEMM ----
    const float inv0 = 1.f / lrow0, inv1 = 1.f / lrow1;
    const int b = bh >> 4, h = bh & 15;
    const int t0 = qb * 128 + wid * 16 + g;
#pragma unroll
    for (int j = 0; j < 8; j++) {
        const int d = j * 8 + t2;
        const size_t i0 = ((size_t)(b * T_ + t0)) * C_ + h * 64 + d;
        const size_t i1 = i0 + (size_t)8 * C_;
        *(uint32_t*)&g_a[i0] = packh2(ofr[j][0] * inv0, ofr[j][1] * inv0);
        *(uint32_t*)&g_a[i1] = packh2(ofr[j][2] * inv1, ofr[j][3] * inv1);
    }
}

// ---------------------------------------------------------------------------
// Launch. Inputs: x, mask, W_attn, b_attn, W_proj, b_proj.
// Output: [out (B,T,C) | k (B,H,T,D) | v (B,H,T,D)] fp32.
// ---------------------------------------------------------------------------
extern "C" void kernel_launch(void* const* d_in, const int* in_sizes, int n_in,
                              void* d_out, int out_size)
{
    (void)in_sizes; (void)n_in; (void)out_size;
    const float* x      = (const float*)d_in[0];
    const float* W_attn = (const float*)d_in[2];
    const float* b_attn = (const float*)d_in[3];
    const float* W_proj = (const float*)d_in[4];
    const float* b_proj = (const float*)d_in[5];

    float* out  = (float*)d_out;
    float* kout = out + (size_t)B_ * H_ * T_ * D_;
    float* vout = kout + (size_t)B_ * H_ * T_ * D_;

    cudaFuncSetAttribute(mma_gemm<0>, cudaFuncAttributeMaxDynamicSharedMemorySize,
                         SMEM_GEMM_BYTES);
    cudaFuncSetAttribute(mma_gemm<1>, cudaFuncAttributeMaxDynamicSharedMemorySize,
                         SMEM_GEMM_BYTES);
    cudaFuncSetAttribute(attn_mma, cudaFuncAttributeMaxDynamicSharedMemorySize,
                         AT_SMEM);

    // 1) fused conversions (x fp16 + both weight transposes)
    convert_all<<<5120, 256>>>(x, W_attn, W_proj);

    // 2) QKV GEMM + bias + scatter (tile 128x128 -> grid 24x64)
    mma_gemm<0><<<dim3(24, 64), 256, SMEM_GEMM_BYTES>>>(b_attn, nullptr, kout, vout);

    // 3) causal flash attention (tensor cores) -> g_a
    attn_mma<<<dim3(16, 64), 256, AT_SMEM>>>();

    // 4) proj GEMM (grid 8x64)
    mma_gemm<1><<<dim3(8, 64), 256, SMEM_GEMM_BYTES>>>(b_proj, out, nullptr, nullptr);
}

// round 12
// speedup vs baseline: 1.8719x; 1.0777x over previous
#include <cuda_runtime.h>
#include <cuda_fp16.h>
#include <cstdint>

// Problem constants
#define B_ 4
#define T_ 2048
#define C_ 1024
#define H_ 16
#define D_ 64
#define BT_ (B_ * T_)            // 8192
#define KDIM 1024

#define QSCALE 0.18033688011112042f   // 0.125 * log2(e)

// ---------------------------------------------------------------------------
// Scratch (device globals). ALL operands single-term fp16.
// ---------------------------------------------------------------------------
__device__ __half g_x[(size_t)BT_ * KDIM];     // x fp16 [B,T,C]
__device__ __half g_w[(size_t)3 * C_ * KDIM];  // W_attn^T [3072][1024]
__device__ __half g_p[(size_t)C_ * KDIM];      // W_proj^T [1024][1024]
__device__ __half g_a[(size_t)BT_ * KDIM];     // attn-out fp16 [B,T,C]
// Q (pre-scaled by QSCALE), K, V fp16 in [B,H,T,D]
__device__ __half g_q[(size_t)BT_ * C_];
__device__ __half g_k[(size_t)BT_ * C_];
__device__ __half g_v[(size_t)BT_ * C_];

// ---------------------------------------------------------------------------
// helpers (sm_80-era PTX — legal at compute_103 base)
// ---------------------------------------------------------------------------
__device__ __forceinline__ uint32_t s2u(const void* p) {
    uint32_t a;
    asm("{ .reg .u64 t; cvta.to.shared.u64 t, %1; cvt.u32.u64 %0, t; }" : "=r"(a) : "l"(p));
    return a;
}
__device__ __forceinline__ uint32_t swz(uint32_t off) {   // SW128
    return off ^ ((off >> 3) & 0x70);
}
__device__ __forceinline__ void cp_async16(uint32_t dst, const void* src) {
    asm volatile("cp.async.cg.shared.global [%0], [%1], 16;" :: "r"(dst), "l"(src) : "memory");
}
__device__ __forceinline__ void ldsm4(uint32_t* r, uint32_t addr) {
    asm volatile("ldmatrix.sync.aligned.m8n8.x4.shared.b16 {%0,%1,%2,%3}, [%4];"
                 : "=r"(r[0]), "=r"(r[1]), "=r"(r[2]), "=r"(r[3]) : "r"(addr));
}
__device__ __forceinline__ void ldsm4t(uint32_t* r, uint32_t addr) {
    asm volatile("ldmatrix.sync.aligned.m8n8.x4.trans.shared.b16 {%0,%1,%2,%3}, [%4];"
                 : "=r"(r[0]), "=r"(r[1]), "=r"(r[2]), "=r"(r[3]) : "r"(addr));
}
__device__ __forceinline__ void mma2(float* c, const uint32_t* a, uint32_t b0, uint32_t b1) {
    asm volatile(
        "mma.sync.aligned.m16n8k16.row.col.f32.f16.f16.f32 "
        "{%0,%1,%2,%3}, {%4,%5,%6,%7}, {%8,%9}, {%0,%1,%2,%3};"
        : "+f"(c[0]), "+f"(c[1]), "+f"(c[2]), "+f"(c[3])
        : "r"(a[0]), "r"(a[1]), "r"(a[2]), "r"(a[3]), "r"(b0), "r"(b1));
}
__device__ __forceinline__ uint32_t packh2(float x, float y) {
    __half2 t; t.x = __float2half(x); t.y = __float2half(y);
    return *(uint32_t*)&t;
}
__device__ __forceinline__ float qred_max(float v) {
    v = fmaxf(v, __shfl_xor_sync(~0u, v, 1));
    return fmaxf(v, __shfl_xor_sync(~0u, v, 2));
}
__device__ __forceinline__ float qred_sum(float v) {
    v += __shfl_xor_sync(~0u, v, 1);
    return v + __shfl_xor_sync(~0u, v, 2);
}

// ---------------------------------------------------------------------------
// Fused conversion kernel (one launch).
// ---------------------------------------------------------------------------
__global__ __launch_bounds__(256)
void convert_all(const float* __restrict__ x,
                 const float* __restrict__ Wattn,
                 const float* __restrict__ Wproj)
{
    const int blk = blockIdx.x;
    if (blk < 1024) {
        const size_t n4 = (size_t)BT_ * KDIM / 4;
        for (size_t i = (size_t)blk * 256 + threadIdx.x; i < n4; i += (size_t)1024 * 256) {
            float4 v = ((const float4*)x)[i];
            ((uint32_t*)g_x)[2 * i]     = packh2(v.x, v.y);
            ((uint32_t*)g_x)[2 * i + 1] = packh2(v.z, v.w);
        }
    } else {
        const int W = (blk < 4096) ? 0 : 1;
        const int bidx = W ? (blk - 4096) : (blk - 1024);
        const int NBX = W ? 32 : 96;
        const int NC = W ? C_ : 3 * C_;
        const float* src = W ? Wproj : Wattn;
        __half* dh = W ? g_p : g_w;
        const int bx = bidx % NBX;
        const int by = bidx / NBX;
        const int tx = threadIdx.x & 31;
        const int ty = threadIdx.x >> 5;
        __shared__ float tile[32][33];
        const int xcol = bx * 32 + tx;
        const int y0 = by * 32;
#pragma unroll
        for (int j = 0; j < 32; j += 8)
            tile[ty + j][tx] = src[(size_t)(y0 + ty + j) * NC + xcol];
        __syncthreads();
        const int ox = y0 + tx;
        const int oyb = bx * 32;
#pragma unroll
        for (int j = 0; j < 32; j += 8)
            dh[(size_t)(oyb + ty + j) * KDIM + ox] = __float2half(tile[tx][ty + j]);
    }
}

// ---------------------------------------------------------------------------
// Plain fp16 GEMM: CTA tile 128x128, 128 threads (4 warps), warp tile 64x64
// (LDSM bytes/FLOP = 1/32 — exactly at crossbar cap). K_chunk=64, 3-stage
// ring, ONE sync per chunk, 2 CTAs/SM (reg budget 256/thread at 128 thr).
// Stage (32KB): [A 16K][B 16K], SW128.
// ---------------------------------------------------------------------------
#define SM_STAGE 32768
#define SMEM_GEMM_BYTES 98304    // 3 stages
#define NCH 16                   // 1024 / 64

template <int MODE>
__global__ __launch_bounds__(128, 2)
void mma_gemm(const float* __restrict__ bias,
              float* __restrict__ o0, float* __restrict__ o1, float* __restrict__ o2)
{
    extern __shared__ __align__(1024) char smem[];
    const uint32_t sm = s2u(smem);
    const int tid = threadIdx.x;
    const int wid = tid >> 5;
    const int lid = tid & 31;
    const int n0 = blockIdx.x * 128;
    const int m0 = blockIdx.y * 128;

    const __half* Ap = (MODE == 0) ? g_x : g_a;
    const __half* Bp = (MODE == 0) ? g_w : g_p;

    // copy plan: 2048 x 16B per stage, 16 per thread
    auto issue_loads = [&](int c, int s) {
        const uint32_t sb = sm + (uint32_t)s * SM_STAGE;
#pragma unroll
        for (int r = 0; r < 16; r++) {
            const int id = tid + r * 128;
            const int row = (id >> 3) & 127;
            const int c16 = id & 7;
            const uint32_t off = swz((uint32_t)(row * 128 + c16 * 16));
            if (id < 1024)
                cp_async16(sb + off, Ap + (size_t)(m0 + row) * KDIM + c * 64 + c16 * 8);
            else
                cp_async16(sb + 16384 + off, Bp + (size_t)(n0 + row) * KDIM + c * 64 + c16 * 8);
        }
        asm volatile("cp.async.commit_group;" ::: "memory");
    };

    const int wm = (wid & 1) * 64;       // warp M origin
    const int wn = (wid >> 1) * 64;      // warp N origin
    const int g = lid >> 2;
    const int tig = lid & 3;
    const int aRow = lid & 15;
    const int aKb = (lid >> 4) * 16;
    const int bRow = ((lid >> 4) & 1) * 8 + (lid & 7);
    const int bKb = ((lid >> 3) & 1) * 16;

    float Cr[4][8][4];                   // [mi 16-slice][n8 slice][quad] = 128 regs
#pragma unroll
    for (int mi = 0; mi < 4; mi++)
#pragma unroll
        for (int j = 0; j < 8; j++)
#pragma unroll
            for (int qi = 0; qi < 4; qi++) Cr[mi][j][qi] = 0.f;

    issue_loads(0, 0);
    issue_loads(1, 1);

    for (int c = 0; c < NCH; c++) {
        const int s = c % 3;
        if (c < NCH - 1) asm volatile("cp.async.wait_group 1;" ::: "memory");
        else             asm volatile("cp.async.wait_group 0;" ::: "memory");
        __syncthreads();
        if (c + 2 < NCH) issue_loads(c + 2, (c + 2) % 3);

        const uint32_t sb = sm + (uint32_t)s * SM_STAGE;
        const uint32_t tA = sb, tB = sb + 16384;

#pragma unroll
        for (int ks = 0; ks < 4; ks++) {
            const int kb = ks * 32;
            uint32_t af[4][4], bf[4][4];
#pragma unroll
            for (int mi = 0; mi < 4; mi++) {
                const uint32_t off = swz((uint32_t)((wm + mi * 16 + aRow) * 128 + kb + aKb));
                ldsm4(af[mi], tA + off);
            }
#pragma unroll
            for (int jp = 0; jp < 4; jp++) {
                const uint32_t off = swz((uint32_t)((wn + jp * 16 + bRow) * 128 + kb + bKb));
                ldsm4(bf[jp], tB + off);
            }
#pragma unroll
            for (int mi = 0; mi < 4; mi++)
#pragma unroll
                for (int j = 0; j < 8; j++) {
                    const int jp = j >> 1, o = (j & 1) * 2;
                    mma2(Cr[mi][j], af[mi], bf[jp][o], bf[jp][o + 1]);
                }
        }
    }

    // ---- epilogue ----
#pragma unroll
    for (int mi = 0; mi < 4; mi++)
#pragma unroll
        for (int j = 0; j < 8; j++) {
            const int col = n0 + wn + (j >> 1) * 16 + (j & 1) * 8 + tig * 2;
            const float2 bb = *(const float2*)(bias + col);
#pragma unroll
            for (int half = 0; half < 2; half++) {
                const int row = m0 + wm + mi * 16 + g + half * 8;
                float2 v;
                v.x = Cr[mi][j][half * 2 + 0] + bb.x;
                v.y = Cr[mi][j][half * 2 + 1] + bb.y;
                if (MODE == 0) {
                    const int seg = col >> 10;
                    const int c0 = col & 1023;
                    const int h = c0 >> 6;
                    const int dd = c0 & 63;
                    const int b = row >> 11;
                    const int t = row & (T_ - 1);
                    const size_t idx = ((size_t)(b * H_ + h) * T_ + t) * D_ + dd;
                    if (seg == 0) {
                        *(uint32_t*)&g_q[idx] = packh2(v.x * QSCALE, v.y * QSCALE);
                    } else if (seg == 1) {
                        *(float2*)&o1[idx] = v;
                        *(uint32_t*)&g_k[idx] = packh2(v.x, v.y);
                    } else {
                        *(float2*)&o2[idx] = v;
                        *(uint32_t*)&g_v[idx] = packh2(v.x, v.y);
                    }
                } else {
                    *(float2*)&o0[(size_t)row * C_ + col] = v;
                }
            }
        }
}

// ---------------------------------------------------------------------------
// Flash attention: 128 threads (4 warps), warp = 32 q-rows (K/V LDSM dup x4,
// halved). CTA: 128 q-rows; KV tile 64; 3-stage KV, single sync, 2 CTAs/SM.
// smem: Q 16KB @0; stage s @16384+s*16384: [K 8KB][V 8KB]
// ---------------------------------------------------------------------------
#define AT_SMEM 65536            // Q 16K + 3 stages x 16K

__global__ __launch_bounds__(128, 2)
void attn_mma()
{
    extern __shared__ __align__(1024) char smem[];
    const uint32_t sm = s2u(smem);
    const int tid = threadIdx.x;
    const int wid = tid >> 5;
    const int lid = tid & 31;
    const int qb = 15 - blockIdx.x;          // heavy CTAs first
    const int bh = blockIdx.y;
    const size_t base_qkv = (size_t)bh * T_ * D_;
    const int nt = 2 * qb + 2;

    // Q loads (folded into group 0): 1024 x 16B, 8 per thread
#pragma unroll
    for (int r = 0; r < 8; r++) {
        const int id = tid + r * 128;
        const int row = id >> 3;
        const int c16 = id & 7;
        const uint32_t dst = sm + swz((uint32_t)(row * 128 + c16 * 16));
        const __half* src = g_q + base_qkv + (size_t)(qb * 128 + row) * D_ + c16 * 8;
        cp_async16(dst, src);
    }
    auto issue_kv = [&](int kt, int s) {
        const uint32_t sb = sm + 16384 + (uint32_t)s * 16384;
#pragma unroll
        for (int r = 0; r < 8; r++) {
            const int id = tid + r * 128;
            const int bsel = id >> 9;        // 0 K 1 V
            const int row = (id >> 3) & 63;
            const int c16 = id & 7;
            const uint32_t dst = sb + bsel * 8192 + swz((uint32_t)(row * 128 + c16 * 16));
            const __half* src = (bsel ? g_v : g_k) + base_qkv
                                + (size_t)(kt * 64 + row) * D_ + c16 * 8;
            cp_async16(dst, src);
        }
        asm volatile("cp.async.commit_group;" ::: "memory");
    };
    issue_kv(0, 0);
    issue_kv(1, 1);

    const int g = lid >> 2;
    const int t2 = (lid & 3) * 2;
    const int lrow16 = lid & 15;
    const int lhi = (lid >> 4) * 16;
    const int wq = wid * 32;                 // warp q origin

    uint32_t qh[2][4][4];                    // [mi][kc][frag]
    float cfr[2][8][4], ofr[2][8][4];        // 64 + 64 regs
    float mr[2][2], lr[2][2];
#pragma unroll
    for (int mi = 0; mi < 2; mi++) {
        mr[mi][0] = -1e30f; mr[mi][1] = -1e30f;
        lr[mi][0] = 0.f;    lr[mi][1] = 0.f;
#pragma unroll
        for (int j = 0; j < 8; j++)
#pragma unroll
            for (int qi = 0; qi < 4; qi++) ofr[mi][j][qi] = 0.f;
    }

    for (int kb = 0; kb < nt; kb++) {
        const int s = kb % 3;
        if (kb + 1 < nt) asm volatile("cp.async.wait_group 1;" ::: "memory");
        else             asm volatile("cp.async.wait_group 0;" ::: "memory");
        __syncthreads();
        if (kb + 2 < nt) issue_kv(kb + 2, (kb + 2) % 3);
        if (kb == 0) {
#pragma unroll
            for (int mi = 0; mi < 2; mi++)
#pragma unroll
                for (int kc = 0; kc < 4; kc++) {
                    const uint32_t off =
                        swz((uint32_t)((wq + mi * 16 + lrow16) * 128 + kc * 32 + lhi));
                    ldsm4(qh[mi][kc], sm + off);
                }
        }
        const uint32_t kvb = sm + 16384 + (uint32_t)s * 16384;

        // ---- S = Q K^T ----
#pragma unroll
        for (int mi = 0; mi < 2; mi++)
#pragma unroll
            for (int j = 0; j < 8; j++)
#pragma unroll
                for (int qi = 0; qi < 4; qi++) cfr[mi][j][qi] = 0.f;
#pragma unroll
        for (int kc = 0; kc < 4; kc++) {
            uint32_t kf[4][4];
#pragma unroll
            for (int jp = 0; jp < 4; jp++) {
                const uint32_t off = swz((uint32_t)((jp * 16 + lrow16) * 128 + kc * 32 + lhi));
                ldsm4(kf[jp], kvb + off);
            }
#pragma unroll
            for (int mi = 0; mi < 2; mi++)
#pragma unroll
                for (int jp = 0; jp < 4; jp++) {
                    mma2(cfr[mi][2 * jp],     qh[mi][kc], kf[jp][0], kf[jp][2]);
                    mma2(cfr[mi][2 * jp + 1], qh[mi][kc], kf[jp][1], kf[jp][3]);
                }
        }

        // ---- causal mask (diagonal tiles only) ----
        if (kb >= 2 * qb) {
            const int kv0 = kb * 64;
#pragma unroll
            for (int mi = 0; mi < 2; mi++) {
                const int qr = qb * 128 + wq + mi * 16 + g;
#pragma unroll
                for (int j = 0; j < 8; j++) {
                    const int col = kv0 + j * 8 + t2;
#pragma unroll
                    for (int qi = 0; qi < 4; qi++) {
                        const int row = qr + ((qi >> 1) << 3);
                        if (col + (qi & 1) > row) cfr[mi][j][qi] = -1e30f;
                    }
                }
            }
        }

        // ---- online softmax (log2 domain) ----
#pragma unroll
        for (int mi = 0; mi < 2; mi++) {
            float mx0 = -1e30f, mx1 = -1e30f;
#pragma unroll
            for (int j = 0; j < 8; j++) {
                mx0 = fmaxf(mx0, fmaxf(cfr[mi][j][0], cfr[mi][j][1]));
                mx1 = fmaxf(mx1, fmaxf(cfr[mi][j][2], cfr[mi][j][3]));
            }
            mx0 = qred_max(mx0);
            mx1 = qred_max(mx1);
            const float mn0 = fmaxf(mr[mi][0], mx0), mn1 = fmaxf(mr[mi][1], mx1);
            const float al0 = exp2f(mr[mi][0] - mn0), al1 = exp2f(mr[mi][1] - mn1);
            mr[mi][0] = mn0; mr[mi][1] = mn1;
            float s0 = 0.f, s1 = 0.f;
#pragma unroll
            for (int j = 0; j < 8; j++) {
                cfr[mi][j][0] = exp2f(cfr[mi][j][0] - mn0);
                cfr[mi][j][1] = exp2f(cfr[mi][j][1] - mn0);
                cfr[mi][j][2] = exp2f(cfr[mi][j][2] - mn1);
                cfr[mi][j][3] = exp2f(cfr[mi][j][3] - mn1);
                s0 += cfr[mi][j][0] + cfr[mi][j][1];
                s1 += cfr[mi][j][2] + cfr[mi][j][3];
            }
            s0 = qred_sum(s0);
            s1 = qred_sum(s1);
            lr[mi][0] = lr[mi][0] * al0 + s0;
            lr[mi][1] = lr[mi][1] * al1 + s1;
#pragma unroll
            for (int j = 0; j < 8; j++) {
                ofr[mi][j][0] *= al0; ofr[mi][j][1] *= al0;
                ofr[mi][j][2] *= al1; ofr[mi][j][3] *= al1;
            }
        }

        // ---- O += P V ----
#pragma unroll
        for (int kc = 0; kc < 4; kc++) {
            uint32_t ph[2][4];
#pragma unroll
            for (int mi = 0; mi < 2; mi++) {
                ph[mi][0] = packh2(cfr[mi][2 * kc][0],     cfr[mi][2 * kc][1]);
                ph[mi][1] = packh2(cfr[mi][2 * kc][2],     cfr[mi][2 * kc][3]);
                ph[mi][2] = packh2(cfr[mi][2 * kc + 1][0], cfr[mi][2 * kc + 1][1]);
                ph[mi][3] = packh2(cfr[mi][2 * kc + 1][2], cfr[mi][2 * kc + 1][3]);
            }
#pragma unroll
            for (int nc = 0; nc < 4; nc++) {
                uint32_t vf[4];
                const uint32_t off = swz((uint32_t)((kc * 16 + lrow16) * 128 + nc * 32 + lhi));
                ldsm4t(vf, kvb + 8192 + off);
#pragma unroll
                for (int mi = 0; mi < 2; mi++) {
                    mma2(ofr[mi][2 * nc],     ph[mi], vf[0], vf[1]);
                    mma2(ofr[mi][2 * nc + 1], ph[mi], vf[2], vf[3]);
                }
            }
        }
    }

    // ---- epilogue: write fp16 into [B,T,C] for proj GEMM ----
    const int b = bh >> 4, h = bh & 15;
#pragma unroll
    for (int mi = 0; mi < 2; mi++) {
        const float inv0 = 1.f / lr[mi][0], inv1 = 1.f / lr[mi][1];
        const int t0 = qb * 128 + wq + mi * 16 + g;
#pragma unroll
        for (int j = 0; j < 8; j++) {
            const int d = j * 8 + t2;
            const size_t i0 = ((size_t)(b * T_ + t0)) * C_ + h * 64 + d;
            const size_t i1 = i0 + (size_t)8 * C_;
            *(uint32_t*)&g_a[i0] = packh2(ofr[mi][j][0] * inv0, ofr[mi][j][1] * inv0);
            *(uint32_t*)&g_a[i1] = packh2(ofr[mi][j][2] * inv1, ofr[mi][j][3] * inv1);
        }
    }
}

// ---------------------------------------------------------------------------
// Launch. Inputs: x, mask, W_attn, b_attn, W_proj, b_proj.
// Output: [out (B,T,C) | k (B,H,T,D) | v (B,H,T,D)] fp32.
// ---------------------------------------------------------------------------
extern "C" void kernel_launch(void* const* d_in, const int* in_sizes, int n_in,
                              void* d_out, int out_size)
{
    (void)in_sizes; (void)n_in; (void)out_size;
    const float* x      = (const float*)d_in[0];
    const float* W_attn = (const float*)d_in[2];
    const float* b_attn = (const float*)d_in[3];
    const float* W_proj = (const float*)d_in[4];
    const float* b_proj = (const float*)d_in[5];

    float* out  = (float*)d_out;
    float* kout = out + (size_t)B_ * H_ * T_ * D_;
    float* vout = kout + (size_t)B_ * H_ * T_ * D_;

    cudaFuncSetAttribute(mma_gemm<0>, cudaFuncAttributeMaxDynamicSharedMemorySize,
                         SMEM_GEMM_BYTES);
    cudaFuncSetAttribute(mma_gemm<1>, cudaFuncAttributeMaxDynamicSharedMemorySize,
                         SMEM_GEMM_BYTES);
    cudaFuncSetAttribute(attn_mma, cudaFuncAttributeMaxDynamicSharedMemorySize,
                         AT_SMEM);

    // 1) fused conversions
    convert_all<<<5120, 256>>>(x, W_attn, W_proj);

    // 2) QKV GEMM + bias + scatter (tile 128x128 -> grid 24x64, 128 thr)
    mma_gemm<0><<<dim3(24, 64), 128, SMEM_GEMM_BYTES>>>(b_attn, nullptr, kout, vout);

    // 3) causal flash attention -> g_a (128 thr)
    attn_mma<<<dim3(16, 64), 128, AT_SMEM>>>();

    // 4) proj GEMM (grid 8x64, 128 thr)
    mma_gemm<1><<<dim3(8, 64), 128, SMEM_GEMM_BYTES>>>(b_proj, out, nullptr, nullptr);
}